// round 10
// baseline (speedup 1.0000x reference)
#include <cuda_runtime.h>
#include <cuda_fp16.h>
#include <math.h>
#include <stdint.h>

#define Vv  32000
#define Ee  512
#define Hh  512
#define Bb  16
#define Ss  128
#define G4  2048   // 4*H
#define MBr 2048   // S*B rows

// ---------------- scratch (static device memory; no allocation) ----------------
__device__ __half g_x0h[(size_t)MBr * Ee];        // layer0 input (fp16)
__device__ __half g_x1h[(size_t)MBr * 1024];      // layer1 input (fp16)
__device__ float  g_xg[2][(size_t)MBr * G4];      // per-dir gate preacts (fp32)
__device__ __half g_hh[2][2][Bb * Hh];            // [parity][dir][b*H] (fp16)
__device__ __half g_hfinh[(size_t)Bb * Ss * 1024];// layer1 output (fp16)
__device__ __half g_wth[(size_t)Vv * 1024];       // lin_w fp16
__device__ __half g_wph[(size_t)4096 * 1024];     // packed Wih fp16 (both dirs)
__device__ float  g_bias[4096];                   // combined bih+bhh (both dirs)
__device__ unsigned g_bar_cnt[2];
__device__ unsigned g_bar_gen[2];

// ================= helpers =================
__device__ __forceinline__ uint32_t smem_u32(const void* p) {
    uint32_t a;
    asm("{ .reg .u64 t; cvta.to.shared.u64 t, %1; cvt.u32.u64 %0, t; }" : "=r"(a) : "l"(p));
    return a;
}
__device__ __forceinline__ void cp16(uint32_t dst, const void* src) {
    asm volatile("cp.async.cg.shared.global [%0], [%1], 16;" :: "r"(dst), "l"(src) : "memory");
}
__device__ __forceinline__ void ldsm_x4(uint32_t* r, uint32_t addr) {
    asm volatile("ldmatrix.sync.aligned.m8n8.x4.shared.b16 {%0,%1,%2,%3}, [%4];"
                 : "=r"(r[0]), "=r"(r[1]), "=r"(r[2]), "=r"(r[3]) : "r"(addr));
}
__device__ __forceinline__ void mma_f16(float* c, const uint32_t* a, uint32_t b0, uint32_t b1) {
    asm volatile(
        "mma.sync.aligned.m16n8k16.row.col.f32.f16.f16.f32 "
        "{%0,%1,%2,%3}, {%4,%5,%6,%7}, {%8,%9}, {%0,%1,%2,%3};\n"
        : "+f"(c[0]), "+f"(c[1]), "+f"(c[2]), "+f"(c[3])
        : "r"(a[0]), "r"(a[1]), "r"(a[2]), "r"(a[3]), "r"(b0), "r"(b1));
}
__device__ __forceinline__ unsigned ld_acq(unsigned* p) {
    unsigned v;
    asm volatile("ld.acquire.gpu.global.u32 %0, [%1];" : "=r"(v) : "l"(p) : "memory");
    return v;
}

// ================= fp16 mma.sync GEMM (128 thr, 64x64 warp tiles) =====
#define RSTR 80                  // bytes per smem row (32 halves + 8 pad)
#define STGB (2 * 128 * RSTR)    // 20480
#define GEMM_DSM 67584           // max(3*STGB=61440, epilogue 128*132*4=67584)

__global__ __launch_bounds__(128) void gemm_mma(
    const __half* __restrict__ A, const __half* __restrict__ Bw,
    const float* __restrict__ bias, float* __restrict__ out,
    int Kdim, int mode)
{
    extern __shared__ char dsmc[];
    float* dsm = reinterpret_cast<float*>(dsmc);
    int tid = threadIdx.x, wid = tid >> 5, lane = tid & 31;
    int warp_m = wid & 1, warp_n = wid >> 1;
    int gr = lane >> 2, gc = lane & 3;
    int m0 = blockIdx.x << 7;
    int n0 = blockIdx.y << 7;
    uint32_t base = smem_u32(dsmc);
    int KC = Kdim >> 5;

    const __half* Ag = A + (size_t)m0 * Kdim;
    const __half* Bg = Bw + (size_t)n0 * Kdim;

    uint32_t aoff = (uint32_t)((lane & 15) * RSTR + (lane >> 4) * 16)
                  + (uint32_t)(warp_m * 64 * RSTR);
    uint32_t boff = (uint32_t)(((lane & 7) + ((lane >> 3) & 1) * 8) * RSTR + (lane >> 4) * 16)
                  + (uint32_t)(warp_n * 64 * RSTR) + 128 * RSTR;

    float acc[4][8][4];
#pragma unroll
    for (int mi = 0; mi < 4; mi++)
#pragma unroll
        for (int ni = 0; ni < 8; ni++)
#pragma unroll
            for (int q = 0; q < 4; q++) acc[mi][ni][q] = 0.f;

#define LOAD_STAGE(s, c) do {                                               \
        uint32_t sb_ = base + (s) * STGB;                                   \
        const __half* Ac_ = Ag + (c) * 32;                                  \
        const __half* Bc_ = Bg + (c) * 32;                                  \
        _Pragma("unroll")                                                   \
        for (int q_ = 0; q_ < 4; q_++) {                                    \
            int f_ = q_ * 128 + tid;                                        \
            int row_ = f_ >> 2, g_ = f_ & 3;                                \
            cp16(sb_ + row_ * RSTR + g_ * 16,                               \
                 Ac_ + (size_t)row_ * Kdim + g_ * 8);                       \
            cp16(sb_ + 128 * RSTR + row_ * RSTR + g_ * 16,                  \
                 Bc_ + (size_t)row_ * Kdim + g_ * 8);                       \
        }                                                                   \
        asm volatile("cp.async.commit_group;" ::: "memory");                \
    } while (0)

    LOAD_STAGE(0, 0);
    LOAD_STAGE(1, 1);
    LOAD_STAGE(2, 2);

    int s = 0;
    for (int c = 0; c < KC; c++) {
        asm volatile("cp.async.wait_group 2;" ::: "memory");
        __syncthreads();
        uint32_t sb = base + s * STGB;
#pragma unroll
        for (int kb = 0; kb < 64; kb += 32) {
            uint32_t af[4][4], bf[4][4];
#pragma unroll
            for (int mi = 0; mi < 4; mi++)
                ldsm_x4(af[mi], sb + aoff + (uint32_t)(mi * 16 * RSTR) + kb);
#pragma unroll
            for (int nj = 0; nj < 4; nj++)
                ldsm_x4(bf[nj], sb + boff + (uint32_t)(nj * 16 * RSTR) + kb);
#pragma unroll
            for (int mi = 0; mi < 4; mi++)
#pragma unroll
                for (int ni = 0; ni < 8; ni++)
                    mma_f16(acc[mi][ni], af[mi],
                            bf[ni >> 1][ni & 1], bf[ni >> 1][2 + (ni & 1)]);
        }
        __syncthreads();
        if (c < KC - 3) LOAD_STAGE(s, c + 3);
        else asm volatile("cp.async.commit_group;" ::: "memory");
        s++; if (s == 3) s = 0;
    }
    asm volatile("cp.async.wait_group 0;" ::: "memory");
    __syncthreads();

    if (mode == 1) {
        float* es = dsm;  // 128 x stride 132
#pragma unroll
        for (int mi = 0; mi < 4; mi++) {
            int row = warp_m * 64 + mi * 16 + gr;
#pragma unroll
            for (int ni = 0; ni < 8; ni++) {
                int col = warp_n * 64 + ni * 8 + gc * 2;
                es[col * 132 + row]           = acc[mi][ni][0];
                es[(col + 1) * 132 + row]     = acc[mi][ni][1];
                es[col * 132 + row + 8]       = acc[mi][ni][2];
                es[(col + 1) * 132 + row + 8] = acc[mi][ni][3];
            }
        }
        __syncthreads();
        int bb = blockIdx.x;
        float* ob = out + (size_t)bb * Vv * Ss;
#pragma unroll 4
        for (int i = 0; i < 32; i++) {
            int f4 = i * 128 + tid;
            int rown = f4 >> 5;
            int c4 = f4 & 31;
            float4 v = *reinterpret_cast<const float4*>(es + rown * 132 + c4 * 4);
            float bv = bias[n0 + rown];
            v.x += bv; v.y += bv; v.z += bv; v.w += bv;
            *reinterpret_cast<float4*>(ob + (size_t)(n0 + rown) * Ss + c4 * 4) = v;
        }
    } else {
        int dirq = n0 >> 11;
        float* dst = out + (size_t)dirq * ((size_t)MBr * G4);
        int ncol0 = n0 & 2047;
#pragma unroll
        for (int mi = 0; mi < 4; mi++) {
            int row = m0 + warp_m * 64 + mi * 16 + gr;
#pragma unroll
            for (int ni = 0; ni < 8; ni++) {
                int nglob = n0 + warp_n * 64 + ni * 8 + gc * 2;
                int col = ncol0 + warp_n * 64 + ni * 8 + gc * 2;
                float bv0 = bias[nglob], bv1 = bias[nglob + 1];
                float2 v0 = make_float2(acc[mi][ni][0] + bv0, acc[mi][ni][1] + bv1);
                float2 v1 = make_float2(acc[mi][ni][2] + bv0, acc[mi][ni][3] + bv1);
                *reinterpret_cast<float2*>(dst + (size_t)row * G4 + col) = v0;
                *reinterpret_cast<float2*>(dst + (size_t)(row + 8) * G4 + col) = v1;
            }
        }
    }
#undef LOAD_STAGE
}

// ---------------- fp32 -> fp16 conversion (vectorized) ----------------
__global__ void cvt_half_kernel(const float* __restrict__ in, __half* __restrict__ out) {
    int i = blockIdx.x * blockDim.x + threadIdx.x;
    float4 v = reinterpret_cast<const float4*>(in)[i];
    reinterpret_cast<__half2*>(out)[2 * i]     = __floats2half2_rn(v.x, v.y);
    reinterpret_cast<__half2*>(out)[2 * i + 1] = __floats2half2_rn(v.z, v.w);
}

// ---------------- combined bias ----------------
__global__ void bias_comb(const float* __restrict__ b1f, const float* __restrict__ b2f,
                          const float* __restrict__ b1b, const float* __restrict__ b2b) {
    int i = blockIdx.x * blockDim.x + threadIdx.x;
    g_bias[i] = b1f[i] + b2f[i];
    g_bias[2048 + i] = b1b[i] + b2b[i];
}

// ---------------- embedding gather (fp16 out) ----------------
__global__ void embed_kernel(const int* __restrict__ tok, const float* __restrict__ ew) {
    int sb = blockIdx.x;
    int s = sb >> 4, b = sb & 15;
    int t = tok[b * Ss + s];
    float4 v = reinterpret_cast<const float4*>(ew + (size_t)t * Ee)[threadIdx.x];
    __half2* dst = reinterpret_cast<__half2*>(g_x0h + (size_t)sb * Ee);
    dst[2 * threadIdx.x]     = __floats2half2_rn(v.x, v.y);
    dst[2 * threadIdx.x + 1] = __floats2half2_rn(v.z, v.w);
}

// ================= persistent LSTM with mma recurrence =================
#define WS16_B 33280                       // 32*520*2
#define HS16_B 16640                       // 16*520*2
#define ZR_OFF (WS16_B + HS16_B)           // 49920
#define LSTM_DSM (ZR_OFF + 32 * 16 * 4)    // 51968

__global__ __launch_bounds__(128) void lstm_persist(
    const float* __restrict__ Whh_f, const float* __restrict__ Whh_b, int mode)
{
    extern __shared__ char sm[];
    __half* ws16 = reinterpret_cast<__half*>(sm);
    float* zr = reinterpret_cast<float*>(sm + ZR_OFF);
    int dir = blockIdx.y;
    int u0 = blockIdx.x << 3;
    int tid = threadIdx.x;
    int wid = tid >> 5, lane = tid & 31;
    int gr = lane >> 2, gc = lane & 3;
    int gb = tid >> 3, gu = tid & 7;
    const float* Whh = dir ? Whh_b : Whh_f;
    uint32_t ws_b = smem_u32(sm);
    uint32_t hs_b = ws_b + WS16_B;

    for (int f4 = tid; f4 < 32 * 128; f4 += 128) {
        int r = f4 >> 7, c4 = f4 & 127;
        int R = (r >> 3) * Hh + u0 + (r & 7);
        float4 v = *reinterpret_cast<const float4*>(Whh + (size_t)R * Hh + (c4 << 2));
        __half2* d = reinterpret_cast<__half2*>(ws16 + r * 520 + (c4 << 2));
        d[0] = __floats2half2_rn(v.x, v.y);
        d[1] = __floats2half2_rn(v.z, v.w);
    }
    __syncthreads();

    uint32_t wreg[16][4];
    {
        uint32_t wrow = ws_b + (uint32_t)((wid * 8 + (lane & 7)) * 1040 + (lane >> 3) * 16);
#pragma unroll
        for (int ks = 0; ks < 16; ks++)
            ldsm_x4(wreg[ks], wrow + (uint32_t)(ks * 64));
    }
    __syncthreads();

    uint32_t a_base = hs_b + (uint32_t)((lane & 15) * 1040 + (lane >> 4) * 16);
    float creg = 0.f;
    unsigned mygen = 0;
    if (tid == 0) mygen = ld_acq(&g_bar_gen[dir]);

    int row = tid >> 3, j = tid & 7;
    for (int t = 0; t < Ss; t++) {
        int tidx = dir ? (Ss - 1 - t) : t;

        {
            uint4* dst4 = reinterpret_cast<uint4*>(sm + WS16_B);
            if (t == 0) {
                uint4 z = make_uint4(0, 0, 0, 0);
#pragma unroll
                for (int jj = 0; jj < 8; jj++) dst4[row * 65 + jj * 8 + j] = z;
            } else {
                const uint4* src4 = reinterpret_cast<const uint4*>(g_hh[t & 1][dir]);
#pragma unroll
                for (int jj = 0; jj < 8; jj++)
                    dst4[row * 65 + jj * 8 + j] = __ldcv(src4 + row * 64 + jj * 8 + j);
            }
        }
        __syncthreads();

        float acc[4] = {0.f, 0.f, 0.f, 0.f};
#pragma unroll
        for (int ks = 0; ks < 32; ks++) {
            uint32_t af[4];
            ldsm_x4(af, a_base + (uint32_t)(ks * 32));
            mma_f16(acc, af, wreg[ks >> 1][(ks & 1) * 2], wreg[ks >> 1][(ks & 1) * 2 + 1]);
        }
        zr[(wid * 8 + 2 * gc) * 16 + gr]         = acc[0];
        zr[(wid * 8 + 2 * gc + 1) * 16 + gr]     = acc[1];
        zr[(wid * 8 + 2 * gc) * 16 + gr + 8]     = acc[2];
        zr[(wid * 8 + 2 * gc + 1) * 16 + gr + 8] = acc[3];
        __syncthreads();

        {
            int unit = u0 + gu;
            const float* xgd = g_xg[dir] + (size_t)(tidx * Bb + gb) * G4 + unit;
            float zi = zr[gu * 16 + gb]        + xgd[0];
            float zf = zr[(8 + gu) * 16 + gb]  + xgd[Hh];
            float zg = zr[(16 + gu) * 16 + gb] + xgd[2 * Hh];
            float zo = zr[(24 + gu) * 16 + gb] + xgd[3 * Hh];
            float ig = 1.f / (1.f + expf(-zi));
            float fg = 1.f / (1.f + expf(-zf));
            float gg = tanhf(zg);
            float og = 1.f / (1.f + expf(-zo));
            creg = fg * creg + ig * gg;
            float h = og * tanhf(creg);
            __half hh = __float2half_rn(h);
            g_hh[(t & 1) ^ 1][dir][gb * Hh + unit] = hh;
            if (mode == 0)
                g_x1h[(size_t)(tidx * Bb + gb) * 1024 + (dir << 9) + unit] = hh;
            else
                g_hfinh[(size_t)gb * (Ss * 1024) + tidx * 1024 + (dir << 9) + unit] = hh;
        }

        __syncthreads();
        if (tid == 0) {
            __threadfence();
            unsigned arrived = atomicAdd(&g_bar_cnt[dir], 1u);
            mygen++;
            if (arrived == 63u) {
                g_bar_cnt[dir] = 0u;
                asm volatile("red.release.gpu.global.add.u32 [%0], 1;"
                             :: "l"(&g_bar_gen[dir]) : "memory");
            } else {
                while (ld_acq(&g_bar_gen[dir]) != mygen) { }
            }
        }
        __syncthreads();
    }
}

// ---------------- launch (with side-stream overlap of conversions) ----------------
static cudaStream_t g_s1 = nullptr;
static cudaEvent_t g_eF = nullptr, g_e1 = nullptr, g_e2 = nullptr;
static int g_stream_init = 0;

extern "C" void kernel_launch(void* const* d_in, const int* in_sizes, int n_in,
                              void* d_out, int out_size)
{
    const int*   tok  = (const int*)d_in[0];
    const float* ew   = (const float*)d_in[1];
    const float* Wih0f = (const float*)d_in[2],  *Whh0f = (const float*)d_in[3];
    const float* bih0f = (const float*)d_in[4],  *bhh0f = (const float*)d_in[5];
    const float* Wih0b = (const float*)d_in[6],  *Whh0b = (const float*)d_in[7];
    const float* bih0b = (const float*)d_in[8],  *bhh0b = (const float*)d_in[9];
    const float* Wih1f = (const float*)d_in[10], *Whh1f = (const float*)d_in[11];
    const float* bih1f = (const float*)d_in[12], *bhh1f = (const float*)d_in[13];
    const float* Wih1b = (const float*)d_in[14], *Whh1b = (const float*)d_in[15];
    const float* bih1b = (const float*)d_in[16], *bhh1b = (const float*)d_in[17];
    const float* linw = (const float*)d_in[18],  *linb  = (const float*)d_in[19];
    float* out = (float*)d_out;

    __half *px0, *px1, *phf, *pwt, *pwp;
    float *pxg, *pbias;
    cudaGetSymbolAddress((void**)&px0, g_x0h);
    cudaGetSymbolAddress((void**)&px1, g_x1h);
    cudaGetSymbolAddress((void**)&pxg, g_xg);
    cudaGetSymbolAddress((void**)&phf, g_hfinh);
    cudaGetSymbolAddress((void**)&pwt, g_wth);
    cudaGetSymbolAddress((void**)&pwp, g_wph);
    cudaGetSymbolAddress((void**)&pbias, g_bias);

    cudaFuncSetAttribute(gemm_mma, cudaFuncAttributeMaxDynamicSharedMemorySize, GEMM_DSM);
    cudaFuncSetAttribute(lstm_persist, cudaFuncAttributeMaxDynamicSharedMemorySize, LSTM_DSM);

    // Lazy stream/event creation on first (uncaptured) call only.
    if (!g_stream_init) {
        g_stream_init = 1;
        cudaStreamCaptureStatus st = cudaStreamCaptureStatusNone;
        cudaStreamIsCapturing((cudaStream_t)0, &st);
        if (st == cudaStreamCaptureStatusNone) {
            if (cudaStreamCreateWithFlags(&g_s1, cudaStreamNonBlocking) != cudaSuccess) g_s1 = nullptr;
            if (g_s1) {
                if (cudaEventCreateWithFlags(&g_eF, cudaEventDisableTiming) != cudaSuccess ||
                    cudaEventCreateWithFlags(&g_e1, cudaEventDisableTiming) != cudaSuccess ||
                    cudaEventCreateWithFlags(&g_e2, cudaEventDisableTiming) != cudaSuccess) {
                    g_s1 = nullptr;
                }
            }
        }
    }
    bool ov = (g_s1 != nullptr);

    if (ov) {
        // fork: big lin_w conversion on side stream
        cudaEventRecord(g_eF, (cudaStream_t)0);
        cudaStreamWaitEvent(g_s1, g_eF, 0);
        cvt_half_kernel<<<(Vv * 1024 / 4) / 256, 256, 0, g_s1>>>(linw, pwt);
    } else {
        cvt_half_kernel<<<(Vv * 1024 / 4) / 256, 256>>>(linw, pwt);
    }

    embed_kernel<<<MBr, 128>>>(tok, ew);

    // ---- layer 0 ----
    cvt_half_kernel<<<(2048 * 512 / 4) / 256, 256>>>(Wih0f, pwp);
    cvt_half_kernel<<<(2048 * 512 / 4) / 256, 256>>>(Wih0b, pwp + (size_t)2048 * 512);
    bias_comb<<<8, 256>>>(bih0f, bhh0f, bih0b, bhh0b);
    gemm_mma<<<dim3(16, 32), 128, GEMM_DSM>>>(px0, pwp, pbias, pxg, 512, 0);

    if (ov) {
        // after xg0 has consumed g_wph/g_bias, side stream prepares layer-1 weights
        cudaEventRecord(g_e1, (cudaStream_t)0);
        cudaStreamWaitEvent(g_s1, g_e1, 0);
        cvt_half_kernel<<<(2048 * 1024 / 4) / 256, 256, 0, g_s1>>>(Wih1f, pwp);
        cvt_half_kernel<<<(2048 * 1024 / 4) / 256, 256, 0, g_s1>>>(Wih1b, pwp + (size_t)2048 * 1024);
        bias_comb<<<8, 256, 0, g_s1>>>(bih1f, bhh1f, bih1b, bhh1b);
        cudaEventRecord(g_e2, g_s1);
    }

    lstm_persist<<<dim3(64, 2), 128, LSTM_DSM>>>(Whh0f, Whh0b, 0);

    // ---- layer 1 ----
    if (ov) {
        cudaStreamWaitEvent((cudaStream_t)0, g_e2, 0);   // join: lin_w + Wih1 + bias1 ready
    } else {
        cvt_half_kernel<<<(2048 * 1024 / 4) / 256, 256>>>(Wih1f, pwp);
        cvt_half_kernel<<<(2048 * 1024 / 4) / 256, 256>>>(Wih1b, pwp + (size_t)2048 * 1024);
        bias_comb<<<8, 256>>>(bih1f, bhh1f, bih1b, bhh1b);
    }
    gemm_mma<<<dim3(16, 32), 128, GEMM_DSM>>>(px1, pwp, pbias, pxg, 1024, 0);
    lstm_persist<<<dim3(64, 2), 128, LSTM_DSM>>>(Whh1f, Whh1b, 1);

    // ---- final projection ----
    gemm_mma<<<dim3(16, 250), 128, GEMM_DSM>>>(phf, pwt, linb, out, 1024, 1);
}

// round 11
// speedup vs baseline: 1.0027x; 1.0027x over previous
#include <cuda_runtime.h>
#include <cuda_fp16.h>
#include <math.h>
#include <stdint.h>

#define Vv  32000
#define Ee  512
#define Hh  512
#define Bb  16
#define Ss  128
#define G4  2048   // 4*H
#define MBr 2048   // S*B rows

// ---------------- scratch (static device memory; no allocation) ----------------
__device__ __half g_x0h[(size_t)MBr * Ee];        // layer0 input (fp16)
__device__ __half g_x1h[(size_t)MBr * 1024];      // layer1 input (fp16)
__device__ float  g_xg[2][(size_t)MBr * G4];      // per-dir gate preacts (fp32)
__device__ __half g_hh[2][2][Bb * Hh];            // [parity][dir][b*H] (fp16)
__device__ __half g_hfinh[(size_t)Bb * Ss * 1024];// layer1 output (fp16)
__device__ __half g_wth[(size_t)Vv * 1024];       // lin_w fp16
__device__ __half g_wph[(size_t)4096 * 1024];     // packed Wih fp16 (both dirs)
__device__ float  g_bias[4096];                   // combined bih+bhh (both dirs)
__device__ unsigned g_bar_cnt[2];
__device__ unsigned g_bar_gen[2];

// ================= helpers =================
__device__ __forceinline__ uint32_t smem_u32(const void* p) {
    uint32_t a;
    asm("{ .reg .u64 t; cvta.to.shared.u64 t, %1; cvt.u32.u64 %0, t; }" : "=r"(a) : "l"(p));
    return a;
}
__device__ __forceinline__ void cp16(uint32_t dst, const void* src) {
    asm volatile("cp.async.cg.shared.global [%0], [%1], 16;" :: "r"(dst), "l"(src) : "memory");
}
__device__ __forceinline__ void ldsm_x4(uint32_t* r, uint32_t addr) {
    asm volatile("ldmatrix.sync.aligned.m8n8.x4.shared.b16 {%0,%1,%2,%3}, [%4];"
                 : "=r"(r[0]), "=r"(r[1]), "=r"(r[2]), "=r"(r[3]) : "r"(addr));
}
__device__ __forceinline__ void mma_f16(float* c, const uint32_t* a, uint32_t b0, uint32_t b1) {
    asm volatile(
        "mma.sync.aligned.m16n8k16.row.col.f32.f16.f16.f32 "
        "{%0,%1,%2,%3}, {%4,%5,%6,%7}, {%8,%9}, {%0,%1,%2,%3};\n"
        : "+f"(c[0]), "+f"(c[1]), "+f"(c[2]), "+f"(c[3])
        : "r"(a[0]), "r"(a[1]), "r"(a[2]), "r"(a[3]), "r"(b0), "r"(b1));
}
__device__ __forceinline__ unsigned ld_acq(unsigned* p) {
    unsigned v;
    asm volatile("ld.acquire.gpu.global.u32 %0, [%1];" : "=r"(v) : "l"(p) : "memory");
    return v;
}

// ================= fp16 mma.sync GEMM (128 thr, 64x64 warp tiles) =====
#define RSTR 80                  // bytes per smem row (32 halves + 8 pad)
#define STGB (2 * 128 * RSTR)    // 20480
#define GEMM_DSM 67584           // max(3*STGB=61440, epilogue 128*132*4=67584)

__global__ __launch_bounds__(128) void gemm_mma(
    const __half* __restrict__ A, const __half* __restrict__ Bw,
    const float* __restrict__ bias, float* __restrict__ out,
    int Kdim, int mode)
{
    extern __shared__ char dsmc[];
    float* dsm = reinterpret_cast<float*>(dsmc);
    int tid = threadIdx.x, wid = tid >> 5, lane = tid & 31;
    int warp_m = wid & 1, warp_n = wid >> 1;
    int gr = lane >> 2, gc = lane & 3;
    int m0 = blockIdx.x << 7;
    int n0 = blockIdx.y << 7;
    uint32_t base = smem_u32(dsmc);
    int KC = Kdim >> 5;

    const __half* Ag = A + (size_t)m0 * Kdim;
    const __half* Bg = Bw + (size_t)n0 * Kdim;

    uint32_t aoff = (uint32_t)((lane & 15) * RSTR + (lane >> 4) * 16)
                  + (uint32_t)(warp_m * 64 * RSTR);
    uint32_t boff = (uint32_t)(((lane & 7) + ((lane >> 3) & 1) * 8) * RSTR + (lane >> 4) * 16)
                  + (uint32_t)(warp_n * 64 * RSTR) + 128 * RSTR;

    float acc[4][8][4];
#pragma unroll
    for (int mi = 0; mi < 4; mi++)
#pragma unroll
        for (int ni = 0; ni < 8; ni++)
#pragma unroll
            for (int q = 0; q < 4; q++) acc[mi][ni][q] = 0.f;

#define LOAD_STAGE(s, c) do {                                               \
        uint32_t sb_ = base + (s) * STGB;                                   \
        const __half* Ac_ = Ag + (c) * 32;                                  \
        const __half* Bc_ = Bg + (c) * 32;                                  \
        _Pragma("unroll")                                                   \
        for (int q_ = 0; q_ < 4; q_++) {                                    \
            int f_ = q_ * 128 + tid;                                        \
            int row_ = f_ >> 2, g_ = f_ & 3;                                \
            cp16(sb_ + row_ * RSTR + g_ * 16,                               \
                 Ac_ + (size_t)row_ * Kdim + g_ * 8);                       \
            cp16(sb_ + 128 * RSTR + row_ * RSTR + g_ * 16,                  \
                 Bc_ + (size_t)row_ * Kdim + g_ * 8);                       \
        }                                                                   \
        asm volatile("cp.async.commit_group;" ::: "memory");                \
    } while (0)

    LOAD_STAGE(0, 0);
    LOAD_STAGE(1, 1);
    LOAD_STAGE(2, 2);

    int s = 0;
    for (int c = 0; c < KC; c++) {
        asm volatile("cp.async.wait_group 2;" ::: "memory");
        __syncthreads();
        uint32_t sb = base + s * STGB;
#pragma unroll
        for (int kb = 0; kb < 64; kb += 32) {
            uint32_t af[4][4], bf[4][4];
#pragma unroll
            for (int mi = 0; mi < 4; mi++)
                ldsm_x4(af[mi], sb + aoff + (uint32_t)(mi * 16 * RSTR) + kb);
#pragma unroll
            for (int nj = 0; nj < 4; nj++)
                ldsm_x4(bf[nj], sb + boff + (uint32_t)(nj * 16 * RSTR) + kb);
#pragma unroll
            for (int mi = 0; mi < 4; mi++)
#pragma unroll
                for (int ni = 0; ni < 8; ni++)
                    mma_f16(acc[mi][ni], af[mi],
                            bf[ni >> 1][ni & 1], bf[ni >> 1][2 + (ni & 1)]);
        }
        __syncthreads();
        if (c < KC - 3) LOAD_STAGE(s, c + 3);
        else asm volatile("cp.async.commit_group;" ::: "memory");
        s++; if (s == 3) s = 0;
    }
    asm volatile("cp.async.wait_group 0;" ::: "memory");
    __syncthreads();

    if (mode == 1) {
        float* es = dsm;  // 128 x stride 132
#pragma unroll
        for (int mi = 0; mi < 4; mi++) {
            int row = warp_m * 64 + mi * 16 + gr;
#pragma unroll
            for (int ni = 0; ni < 8; ni++) {
                int col = warp_n * 64 + ni * 8 + gc * 2;
                es[col * 132 + row]           = acc[mi][ni][0];
                es[(col + 1) * 132 + row]     = acc[mi][ni][1];
                es[col * 132 + row + 8]       = acc[mi][ni][2];
                es[(col + 1) * 132 + row + 8] = acc[mi][ni][3];
            }
        }
        __syncthreads();
        int bb = blockIdx.x;
        float* ob = out + (size_t)bb * Vv * Ss;
#pragma unroll 4
        for (int i = 0; i < 32; i++) {
            int f4 = i * 128 + tid;
            int rown = f4 >> 5;
            int c4 = f4 & 31;
            float4 v = *reinterpret_cast<const float4*>(es + rown * 132 + c4 * 4);
            float bv = bias[n0 + rown];
            v.x += bv; v.y += bv; v.z += bv; v.w += bv;
            *reinterpret_cast<float4*>(ob + (size_t)(n0 + rown) * Ss + c4 * 4) = v;
        }
    } else {
        int dirq = n0 >> 11;
        float* dst = out + (size_t)dirq * ((size_t)MBr * G4);
        int ncol0 = n0 & 2047;
#pragma unroll
        for (int mi = 0; mi < 4; mi++) {
            int row = m0 + warp_m * 64 + mi * 16 + gr;
#pragma unroll
            for (int ni = 0; ni < 8; ni++) {
                int nglob = n0 + warp_n * 64 + ni * 8 + gc * 2;
                int col = ncol0 + warp_n * 64 + ni * 8 + gc * 2;
                float bv0 = bias[nglob], bv1 = bias[nglob + 1];
                float2 v0 = make_float2(acc[mi][ni][0] + bv0, acc[mi][ni][1] + bv1);
                float2 v1 = make_float2(acc[mi][ni][2] + bv0, acc[mi][ni][3] + bv1);
                *reinterpret_cast<float2*>(dst + (size_t)row * G4 + col) = v0;
                *reinterpret_cast<float2*>(dst + (size_t)(row + 8) * G4 + col) = v1;
            }
        }
    }
#undef LOAD_STAGE
}

// ---------------- fp32 -> fp16 conversion (2 float4 per thread, MLP=2) ----------------
__global__ void cvt_half_kernel(const float* __restrict__ in, __half* __restrict__ out, int n4) {
    int i = blockIdx.x * blockDim.x + threadIdx.x;
    int half4 = n4 >> 1;
    if (i < half4) {
        float4 v0 = reinterpret_cast<const float4*>(in)[i];
        float4 v1 = reinterpret_cast<const float4*>(in)[i + half4];
        __half2* o = reinterpret_cast<__half2*>(out);
        o[2 * i]     = __floats2half2_rn(v0.x, v0.y);
        o[2 * i + 1] = __floats2half2_rn(v0.z, v0.w);
        o[2 * (i + half4)]     = __floats2half2_rn(v1.x, v1.y);
        o[2 * (i + half4) + 1] = __floats2half2_rn(v1.z, v1.w);
    }
}

// ---------------- paired weight conversion (f and b halves in one launch) -------------
__global__ void cvt_half2_kernel(const float* __restrict__ inf, const float* __restrict__ inb,
                                 __half* __restrict__ out, int n4each) {
    int i = blockIdx.x * blockDim.x + threadIdx.x;
    if (i < n4each) {
        float4 v0 = reinterpret_cast<const float4*>(inf)[i];
        float4 v1 = reinterpret_cast<const float4*>(inb)[i];
        __half2* o = reinterpret_cast<__half2*>(out);
        o[2 * i]     = __floats2half2_rn(v0.x, v0.y);
        o[2 * i + 1] = __floats2half2_rn(v0.z, v0.w);
        o[2 * (i + n4each)]     = __floats2half2_rn(v1.x, v1.y);
        o[2 * (i + n4each) + 1] = __floats2half2_rn(v1.z, v1.w);
    }
}

// ---------------- combined bias ----------------
__global__ void bias_comb(const float* __restrict__ b1f, const float* __restrict__ b2f,
                          const float* __restrict__ b1b, const float* __restrict__ b2b) {
    int i = blockIdx.x * blockDim.x + threadIdx.x;
    g_bias[i] = b1f[i] + b2f[i];
    g_bias[2048 + i] = b1b[i] + b2b[i];
}

// ---------------- embedding gather (fp16 out) ----------------
__global__ void embed_kernel(const int* __restrict__ tok, const float* __restrict__ ew) {
    int sb = blockIdx.x;
    int s = sb >> 4, b = sb & 15;
    int t = tok[b * Ss + s];
    float4 v = reinterpret_cast<const float4*>(ew + (size_t)t * Ee)[threadIdx.x];
    __half2* dst = reinterpret_cast<__half2*>(g_x0h + (size_t)sb * Ee);
    dst[2 * threadIdx.x]     = __floats2half2_rn(v.x, v.y);
    dst[2 * threadIdx.x + 1] = __floats2half2_rn(v.z, v.w);
}

// ================= persistent LSTM with mma recurrence =================
#define WS16_B 33280                       // 32*520*2
#define HS16_B 16640                       // 16*520*2
#define ZR_OFF (WS16_B + HS16_B)           // 49920
#define LSTM_DSM (ZR_OFF + 32 * 16 * 4)    // 51968

__global__ __launch_bounds__(128) void lstm_persist(
    const float* __restrict__ Whh_f, const float* __restrict__ Whh_b, int mode)
{
    extern __shared__ char sm[];
    __half* ws16 = reinterpret_cast<__half*>(sm);
    float* zr = reinterpret_cast<float*>(sm + ZR_OFF);
    int dir = blockIdx.y;
    int u0 = blockIdx.x << 3;
    int tid = threadIdx.x;
    int wid = tid >> 5, lane = tid & 31;
    int gr = lane >> 2, gc = lane & 3;
    int gb = tid >> 3, gu = tid & 7;
    const float* Whh = dir ? Whh_b : Whh_f;
    uint32_t ws_b = smem_u32(sm);
    uint32_t hs_b = ws_b + WS16_B;

    for (int f4 = tid; f4 < 32 * 128; f4 += 128) {
        int r = f4 >> 7, c4 = f4 & 127;
        int R = (r >> 3) * Hh + u0 + (r & 7);
        float4 v = *reinterpret_cast<const float4*>(Whh + (size_t)R * Hh + (c4 << 2));
        __half2* d = reinterpret_cast<__half2*>(ws16 + r * 520 + (c4 << 2));
        d[0] = __floats2half2_rn(v.x, v.y);
        d[1] = __floats2half2_rn(v.z, v.w);
    }
    __syncthreads();

    uint32_t wreg[16][4];
    {
        uint32_t wrow = ws_b + (uint32_t)((wid * 8 + (lane & 7)) * 1040 + (lane >> 3) * 16);
#pragma unroll
        for (int ks = 0; ks < 16; ks++)
            ldsm_x4(wreg[ks], wrow + (uint32_t)(ks * 64));
    }
    __syncthreads();

    uint32_t a_base = hs_b + (uint32_t)((lane & 15) * 1040 + (lane >> 4) * 16);
    float creg = 0.f;
    unsigned mygen = 0;
    if (tid == 0) mygen = ld_acq(&g_bar_gen[dir]);

    int row = tid >> 3, j = tid & 7;
    for (int t = 0; t < Ss; t++) {
        int tidx = dir ? (Ss - 1 - t) : t;

        {
            uint4* dst4 = reinterpret_cast<uint4*>(sm + WS16_B);
            if (t == 0) {
                uint4 z = make_uint4(0, 0, 0, 0);
#pragma unroll
                for (int jj = 0; jj < 8; jj++) dst4[row * 65 + jj * 8 + j] = z;
            } else {
                const uint4* src4 = reinterpret_cast<const uint4*>(g_hh[t & 1][dir]);
#pragma unroll
                for (int jj = 0; jj < 8; jj++)
                    dst4[row * 65 + jj * 8 + j] = __ldcv(src4 + row * 64 + jj * 8 + j);
            }
        }
        __syncthreads();

        float acc[4] = {0.f, 0.f, 0.f, 0.f};
#pragma unroll
        for (int ks = 0; ks < 32; ks++) {
            uint32_t af[4];
            ldsm_x4(af, a_base + (uint32_t)(ks * 32));
            mma_f16(acc, af, wreg[ks >> 1][(ks & 1) * 2], wreg[ks >> 1][(ks & 1) * 2 + 1]);
        }
        zr[(wid * 8 + 2 * gc) * 16 + gr]         = acc[0];
        zr[(wid * 8 + 2 * gc + 1) * 16 + gr]     = acc[1];
        zr[(wid * 8 + 2 * gc) * 16 + gr + 8]     = acc[2];
        zr[(wid * 8 + 2 * gc + 1) * 16 + gr + 8] = acc[3];
        __syncthreads();

        {
            int unit = u0 + gu;
            const float* xgd = g_xg[dir] + (size_t)(tidx * Bb + gb) * G4 + unit;
            float zi = zr[gu * 16 + gb]        + xgd[0];
            float zf = zr[(8 + gu) * 16 + gb]  + xgd[Hh];
            float zg = zr[(16 + gu) * 16 + gb] + xgd[2 * Hh];
            float zo = zr[(24 + gu) * 16 + gb] + xgd[3 * Hh];
            float ig = 1.f / (1.f + expf(-zi));
            float fg = 1.f / (1.f + expf(-zf));
            float gg = tanhf(zg);
            float og = 1.f / (1.f + expf(-zo));
            creg = fg * creg + ig * gg;
            float h = og * tanhf(creg);
            __half hh = __float2half_rn(h);
            g_hh[(t & 1) ^ 1][dir][gb * Hh + unit] = hh;
            if (mode == 0)
                g_x1h[(size_t)(tidx * Bb + gb) * 1024 + (dir << 9) + unit] = hh;
            else
                g_hfinh[(size_t)gb * (Ss * 1024) + tidx * 1024 + (dir << 9) + unit] = hh;
        }

        __syncthreads();
        if (tid == 0) {
            __threadfence();
            unsigned arrived = atomicAdd(&g_bar_cnt[dir], 1u);
            mygen++;
            if (arrived == 63u) {
                g_bar_cnt[dir] = 0u;
                asm volatile("red.release.gpu.global.add.u32 [%0], 1;"
                             :: "l"(&g_bar_gen[dir]) : "memory");
            } else {
                while (ld_acq(&g_bar_gen[dir]) != mygen) { }
            }
        }
        __syncthreads();
    }
}

// ---------------- launch (sequential; overlap reverted) ----------------
extern "C" void kernel_launch(void* const* d_in, const int* in_sizes, int n_in,
                              void* d_out, int out_size)
{
    const int*   tok  = (const int*)d_in[0];
    const float* ew   = (const float*)d_in[1];
    const float* Wih0f = (const float*)d_in[2],  *Whh0f = (const float*)d_in[3];
    const float* bih0f = (const float*)d_in[4],  *bhh0f = (const float*)d_in[5];
    const float* Wih0b = (const float*)d_in[6],  *Whh0b = (const float*)d_in[7];
    const float* bih0b = (const float*)d_in[8],  *bhh0b = (const float*)d_in[9];
    const float* Wih1f = (const float*)d_in[10], *Whh1f = (const float*)d_in[11];
    const float* bih1f = (const float*)d_in[12], *bhh1f = (const float*)d_in[13];
    const float* Wih1b = (const float*)d_in[14], *Whh1b = (const float*)d_in[15];
    const float* bih1b = (const float*)d_in[16], *bhh1b = (const float*)d_in[17];
    const float* linw = (const float*)d_in[18],  *linb  = (const float*)d_in[19];
    float* out = (float*)d_out;

    __half *px0, *px1, *phf, *pwt, *pwp;
    float *pxg, *pbias;
    cudaGetSymbolAddress((void**)&px0, g_x0h);
    cudaGetSymbolAddress((void**)&px1, g_x1h);
    cudaGetSymbolAddress((void**)&pxg, g_xg);
    cudaGetSymbolAddress((void**)&phf, g_hfinh);
    cudaGetSymbolAddress((void**)&pwt, g_wth);
    cudaGetSymbolAddress((void**)&pwp, g_wph);
    cudaGetSymbolAddress((void**)&pbias, g_bias);

    cudaFuncSetAttribute(gemm_mma, cudaFuncAttributeMaxDynamicSharedMemorySize, GEMM_DSM);
    cudaFuncSetAttribute(lstm_persist, cudaFuncAttributeMaxDynamicSharedMemorySize, LSTM_DSM);

    embed_kernel<<<MBr, 128>>>(tok, ew);
    {   // lin_w: 8.192M float4 -> 4.096M threads (2 float4 each)
        int n4 = Vv * 1024 / 4;
        cvt_half_kernel<<<(n4 / 2 + 255) / 256, 256>>>(linw, pwt, n4);
    }

    // ---- layer 0 ----
    {   // Wih0 f+b in one launch: 2048*512 elems each
        int n4 = 2048 * 512 / 4;
        cvt_half2_kernel<<<(n4 + 255) / 256, 256>>>(Wih0f, Wih0b, pwp, n4);
    }
    bias_comb<<<8, 256>>>(bih0f, bhh0f, bih0b, bhh0b);
    gemm_mma<<<dim3(16, 32), 128, GEMM_DSM>>>(px0, pwp, pbias, pxg, 512, 0);
    lstm_persist<<<dim3(64, 2), 128, LSTM_DSM>>>(Whh0f, Whh0b, 0);

    // ---- layer 1 ----
    {   // Wih1 f+b in one launch: 2048*1024 elems each
        int n4 = 2048 * 1024 / 4;
        cvt_half2_kernel<<<(n4 + 255) / 256, 256>>>(Wih1f, Wih1b, pwp, n4);
    }
    bias_comb<<<8, 256>>>(bih1f, bhh1f, bih1b, bhh1b);
    gemm_mma<<<dim3(16, 32), 128, GEMM_DSM>>>(px1, pwp, pbias, pxg, 1024, 0);
    lstm_persist<<<dim3(64, 2), 128, LSTM_DSM>>>(Whh1f, Whh1b, 1);

    // ---- final projection ----
    gemm_mma<<<dim3(16, 250), 128, GEMM_DSM>>>(phf, pwt, linb, out, 1024, 1);
}

// round 12
// speedup vs baseline: 1.0347x; 1.0320x over previous
#include <cuda_runtime.h>
#include <cuda_fp16.h>
#include <math.h>
#include <stdint.h>

#define Vv  32000
#define Ee  512
#define Hh  512
#define Bb  16
#define Ss  128
#define G4  2048   // 4*H
#define MBr 2048   // S*B rows

// ---------------- scratch (static device memory; no allocation) ----------------
__device__ __half g_x0h[(size_t)MBr * Ee];        // layer0 input (fp16)
__device__ __half g_x1h[(size_t)MBr * 1024];      // layer1 input (fp16)
__device__ float  g_xg[2][(size_t)MBr * G4];      // per-dir gate preacts (fp32)
__device__ __half g_hh[2][2][Bb * Hh];            // [parity][dir][b*H] (fp16)
__device__ __half g_hfinh[(size_t)Bb * Ss * 1024];// layer1 output (fp16)
__device__ float  g_bias[4096];                   // combined bih+bhh (both dirs)
__device__ unsigned g_bar_cnt[2];
__device__ unsigned g_bar_gen[2];

// ================= helpers =================
__device__ __forceinline__ uint32_t smem_u32(const void* p) {
    uint32_t a;
    asm("{ .reg .u64 t; cvta.to.shared.u64 t, %1; cvt.u32.u64 %0, t; }" : "=r"(a) : "l"(p));
    return a;
}
__device__ __forceinline__ void cp16(uint32_t dst, const void* src) {
    asm volatile("cp.async.cg.shared.global [%0], [%1], 16;" :: "r"(dst), "l"(src) : "memory");
}
__device__ __forceinline__ void ldsm_x4(uint32_t* r, uint32_t addr) {
    asm volatile("ldmatrix.sync.aligned.m8n8.x4.shared.b16 {%0,%1,%2,%3}, [%4];"
                 : "=r"(r[0]), "=r"(r[1]), "=r"(r[2]), "=r"(r[3]) : "r"(addr));
}
__device__ __forceinline__ void mma_f16(float* c, const uint32_t* a, uint32_t b0, uint32_t b1) {
    asm volatile(
        "mma.sync.aligned.m16n8k16.row.col.f32.f16.f16.f32 "
        "{%0,%1,%2,%3}, {%4,%5,%6,%7}, {%8,%9}, {%0,%1,%2,%3};\n"
        : "+f"(c[0]), "+f"(c[1]), "+f"(c[2]), "+f"(c[3])
        : "r"(a[0]), "r"(a[1]), "r"(a[2]), "r"(a[3]), "r"(b0), "r"(b1));
}
__device__ __forceinline__ unsigned ld_acq(unsigned* p) {
    unsigned v;
    asm volatile("ld.acquire.gpu.global.u32 %0, [%1];" : "=r"(v) : "l"(p) : "memory");
    return v;
}

// ================= fp16 mma GEMM with fused fp32->fp16 B conversion =================
// 256 threads, 8 warps (2x4), 64x32 warp tiles, CTA tile 128x128, BK=32 halves.
// A: fp16 in gmem, cp.async 3-stage pipeline.
// B: fp32 in gmem (weights), LDG->cvt->STS single-buffered register prefetch.
// mode 0: C = A[M,K]*Bw[4096,K]^T + bias -> g_xg (dir split at n=2048)
// mode 1: N=32000 -> out[B,V,S] scatter
#define RSTR 80                    // bytes per smem row (32 halves + 8 pad)
#define ASTG (128 * RSTR)          // 10240 per A stage
#define BBASE (3 * ASTG)           // B stages start at 30720
#define GEMM_DSM 67584             // max(6*10240=61440, epilogue 128*132*4=67584)

__global__ __launch_bounds__(256, 2) void gemm_mma(
    const __half* __restrict__ A,
    const float* __restrict__ Bf32a, const float* __restrict__ Bf32b,
    const float* __restrict__ bias, float* __restrict__ out,
    int Kdim, int mode)
{
    extern __shared__ char dsmc[];
    float* dsm = reinterpret_cast<float*>(dsmc);
    int tid = threadIdx.x, wid = tid >> 5, lane = tid & 31;
    int warp_m = wid & 1, warp_n = wid >> 1;
    int gr = lane >> 2, gc = lane & 3;
    int m0 = blockIdx.x << 7;
    int n0 = blockIdx.y << 7;
    uint32_t base = smem_u32(dsmc);
    int KC = Kdim >> 5;

    const __half* Ag = A + (size_t)m0 * Kdim;
    const float* Bg = (mode == 0 && n0 >= 2048)
                    ? Bf32b + (size_t)(n0 - 2048) * Kdim
                    : Bf32a + (size_t)n0 * Kdim;

    // B load assignment: thread t covers rows (t>>3)+{0,32,64,96}, float4-group g=t&7
    int brow0 = tid >> 3, bg = tid & 7;
    const float* Bp = Bg + (size_t)brow0 * Kdim + bg * 4;

    uint32_t aoff = (uint32_t)((lane & 15) * RSTR + (lane >> 4) * 16)
                  + (uint32_t)(warp_m * 64 * RSTR);
    uint32_t boff = (uint32_t)(((lane & 7) + ((lane >> 3) & 1) * 8) * RSTR + (lane >> 4) * 16)
                  + (uint32_t)(warp_n * 32 * RSTR);

    float acc[4][4][4];
#pragma unroll
    for (int mi = 0; mi < 4; mi++)
#pragma unroll
        for (int ni = 0; ni < 4; ni++)
#pragma unroll
            for (int q = 0; q < 4; q++) acc[mi][ni][q] = 0.f;

#define LOAD_A(s, c) do {                                                   \
        uint32_t sb_ = base + (s) * ASTG;                                   \
        const __half* Ac_ = Ag + (c) * 32;                                  \
        _Pragma("unroll")                                                   \
        for (int q_ = 0; q_ < 2; q_++) {                                    \
            int f_ = q_ * 256 + tid;                                        \
            int row_ = f_ >> 2, g_ = f_ & 3;                                \
            cp16(sb_ + row_ * RSTR + g_ * 16,                               \
                 Ac_ + (size_t)row_ * Kdim + g_ * 8);                       \
        }                                                                   \
        asm volatile("cp.async.commit_group;" ::: "memory");                \
    } while (0)

#define STS_B(s, v) do {                                                    \
        char* bs_ = dsmc + BBASE + (s) * ASTG;                              \
        _Pragma("unroll")                                                   \
        for (int k_ = 0; k_ < 4; k_++) {                                    \
            __half2* d_ = reinterpret_cast<__half2*>(                       \
                bs_ + (brow0 + k_ * 32) * RSTR + bg * 8);                   \
            d_[0] = __floats2half2_rn((v)[k_].x, (v)[k_].y);                \
            d_[1] = __floats2half2_rn((v)[k_].z, (v)[k_].w);                \
        }                                                                   \
    } while (0)

#define LDG_B(c, v) do {                                                    \
        const float* p_ = Bp + (c) * 32;                                    \
        _Pragma("unroll")                                                   \
        for (int k_ = 0; k_ < 4; k_++)                                      \
            (v)[k_] = *reinterpret_cast<const float4*>(p_ + (size_t)(k_ * 32) * Kdim); \
    } while (0)

    // prologue: A stages 0..2 via cp.async; B stages 0..2 synchronously; B chunk 3 into regs
    LOAD_A(0, 0);
    LOAD_A(1, 1);
    LOAD_A(2, 2);
    {
        float4 v[4];
#pragma unroll
        for (int c = 0; c < 3; c++) { LDG_B(c, v); STS_B(c, v); }
    }
    float4 bb[4];
    LDG_B(3, bb);

    int s = 0;
    for (int c = 0; c < KC; c++) {
        asm volatile("cp.async.wait_group 2;" ::: "memory");
        __syncthreads();
        uint32_t sa = base + s * ASTG;
        uint32_t sb = base + BBASE + s * ASTG;
#pragma unroll
        for (int kb = 0; kb < 64; kb += 32) {
            uint32_t af[4][4], bf[2][4];
#pragma unroll
            for (int mi = 0; mi < 4; mi++)
                ldsm_x4(af[mi], sa + aoff + (uint32_t)(mi * 16 * RSTR) + kb);
#pragma unroll
            for (int nj = 0; nj < 2; nj++)
                ldsm_x4(bf[nj], sb + boff + (uint32_t)(nj * 16 * RSTR) + kb);
#pragma unroll
            for (int mi = 0; mi < 4; mi++)
#pragma unroll
                for (int ni = 0; ni < 4; ni++)
                    mma_f16(acc[mi][ni], af[mi],
                            bf[ni >> 1][ni & 1], bf[ni >> 1][2 + (ni & 1)]);
        }
        __syncthreads();
        if (c + 3 < KC) {
            STS_B(s, bb);                    // chunk c+3 (loaded last iter)
            if (c + 4 < KC) LDG_B(c + 4, bb);
            LOAD_A(s, c + 3);
        } else {
            asm volatile("cp.async.commit_group;" ::: "memory");
        }
        s++; if (s == 3) s = 0;
    }
    asm volatile("cp.async.wait_group 0;" ::: "memory");
    __syncthreads();

    if (mode == 1) {
        float* es = dsm;  // 128 cols x stride 132
#pragma unroll
        for (int mi = 0; mi < 4; mi++) {
            int row = warp_m * 64 + mi * 16 + gr;
#pragma unroll
            for (int ni = 0; ni < 4; ni++) {
                int col = warp_n * 32 + ni * 8 + gc * 2;
                es[col * 132 + row]           = acc[mi][ni][0];
                es[(col + 1) * 132 + row]     = acc[mi][ni][1];
                es[col * 132 + row + 8]       = acc[mi][ni][2];
                es[(col + 1) * 132 + row + 8] = acc[mi][ni][3];
            }
        }
        __syncthreads();
        int bb2 = blockIdx.x;
        float* ob = out + (size_t)bb2 * Vv * Ss;
#pragma unroll 4
        for (int i = 0; i < 16; i++) {
            int f4 = i * 256 + tid;
            int rown = f4 >> 5;
            int c4 = f4 & 31;
            float4 v = *reinterpret_cast<const float4*>(es + rown * 132 + c4 * 4);
            float bv = bias[n0 + rown];
            v.x += bv; v.y += bv; v.z += bv; v.w += bv;
            *reinterpret_cast<float4*>(ob + (size_t)(n0 + rown) * Ss + c4 * 4) = v;
        }
    } else {
        int dirq = n0 >> 11;
        float* dst = out + (size_t)dirq * ((size_t)MBr * G4);
        int ncol0 = n0 & 2047;
#pragma unroll
        for (int mi = 0; mi < 4; mi++) {
            int row = m0 + warp_m * 64 + mi * 16 + gr;
#pragma unroll
            for (int ni = 0; ni < 4; ni++) {
                int nglob = n0 + warp_n * 32 + ni * 8 + gc * 2;
                int col = ncol0 + warp_n * 32 + ni * 8 + gc * 2;
                float bv0 = bias[nglob], bv1 = bias[nglob + 1];
                float2 v0 = make_float2(acc[mi][ni][0] + bv0, acc[mi][ni][1] + bv1);
                float2 v1 = make_float2(acc[mi][ni][2] + bv0, acc[mi][ni][3] + bv1);
                *reinterpret_cast<float2*>(dst + (size_t)row * G4 + col) = v0;
                *reinterpret_cast<float2*>(dst + (size_t)(row + 8) * G4 + col) = v1;
            }
        }
    }
#undef LOAD_A
#undef STS_B
#undef LDG_B
}

// ---------------- combined bias ----------------
__global__ void bias_comb(const float* __restrict__ b1f, const float* __restrict__ b2f,
                          const float* __restrict__ b1b, const float* __restrict__ b2b) {
    int i = blockIdx.x * blockDim.x + threadIdx.x;
    g_bias[i] = b1f[i] + b2f[i];
    g_bias[2048 + i] = b1b[i] + b2b[i];
}

// ---------------- embedding gather (fp16 out) ----------------
__global__ void embed_kernel(const int* __restrict__ tok, const float* __restrict__ ew) {
    int sb = blockIdx.x;
    int s = sb >> 4, b = sb & 15;
    int t = tok[b * Ss + s];
    float4 v = reinterpret_cast<const float4*>(ew + (size_t)t * Ee)[threadIdx.x];
    __half2* dst = reinterpret_cast<__half2*>(g_x0h + (size_t)sb * Ee);
    dst[2 * threadIdx.x]     = __floats2half2_rn(v.x, v.y);
    dst[2 * threadIdx.x + 1] = __floats2half2_rn(v.z, v.w);
}

// ================= persistent LSTM with mma recurrence =================
#define WS16_B 33280                       // 32*520*2
#define HS16_B 16640                       // 16*520*2
#define ZR_OFF (WS16_B + HS16_B)           // 49920
#define LSTM_DSM (ZR_OFF + 32 * 16 * 4)    // 51968

__global__ __launch_bounds__(128) void lstm_persist(
    const float* __restrict__ Whh_f, const float* __restrict__ Whh_b, int mode)
{
    extern __shared__ char sm[];
    __half* ws16 = reinterpret_cast<__half*>(sm);
    float* zr = reinterpret_cast<float*>(sm + ZR_OFF);
    int dir = blockIdx.y;
    int u0 = blockIdx.x << 3;
    int tid = threadIdx.x;
    int wid = tid >> 5, lane = tid & 31;
    int gr = lane >> 2, gc = lane & 3;
    int gb = tid >> 3, gu = tid & 7;
    const float* Whh = dir ? Whh_b : Whh_f;
    uint32_t ws_b = smem_u32(sm);
    uint32_t hs_b = ws_b + WS16_B;

    for (int f4 = tid; f4 < 32 * 128; f4 += 128) {
        int r = f4 >> 7, c4 = f4 & 127;
        int R = (r >> 3) * Hh + u0 + (r & 7);
        float4 v = *reinterpret_cast<const float4*>(Whh + (size_t)R * Hh + (c4 << 2));
        __half2* d = reinterpret_cast<__half2*>(ws16 + r * 520 + (c4 << 2));
        d[0] = __floats2half2_rn(v.x, v.y);
        d[1] = __floats2half2_rn(v.z, v.w);
    }
    __syncthreads();

    uint32_t wreg[16][4];
    {
        uint32_t wrow = ws_b + (uint32_t)((wid * 8 + (lane & 7)) * 1040 + (lane >> 3) * 16);
#pragma unroll
        for (int ks = 0; ks < 16; ks++)
            ldsm_x4(wreg[ks], wrow + (uint32_t)(ks * 64));
    }
    __syncthreads();

    uint32_t a_base = hs_b + (uint32_t)((lane & 15) * 1040 + (lane >> 4) * 16);
    float creg = 0.f;
    unsigned mygen = 0;
    if (tid == 0) mygen = ld_acq(&g_bar_gen[dir]);

    int row = tid >> 3, j = tid & 7;
    for (int t = 0; t < Ss; t++) {
        int tidx = dir ? (Ss - 1 - t) : t;

        {
            uint4* dst4 = reinterpret_cast<uint4*>(sm + WS16_B);
            if (t == 0) {
                uint4 z = make_uint4(0, 0, 0, 0);
#pragma unroll
                for (int jj = 0; jj < 8; jj++) dst4[row * 65 + jj * 8 + j] = z;
            } else {
                const uint4* src4 = reinterpret_cast<const uint4*>(g_hh[t & 1][dir]);
#pragma unroll
                for (int jj = 0; jj < 8; jj++)
                    dst4[row * 65 + jj * 8 + j] = __ldcv(src4 + row * 64 + jj * 8 + j);
            }
        }
        __syncthreads();

        float acc[4] = {0.f, 0.f, 0.f, 0.f};
#pragma unroll
        for (int ks = 0; ks < 32; ks++) {
            uint32_t af[4];
            ldsm_x4(af, a_base + (uint32_t)(ks * 32));
            mma_f16(acc, af, wreg[ks >> 1][(ks & 1) * 2], wreg[ks >> 1][(ks & 1) * 2 + 1]);
        }
        zr[(wid * 8 + 2 * gc) * 16 + gr]         = acc[0];
        zr[(wid * 8 + 2 * gc + 1) * 16 + gr]     = acc[1];
        zr[(wid * 8 + 2 * gc) * 16 + gr + 8]     = acc[2];
        zr[(wid * 8 + 2 * gc + 1) * 16 + gr + 8] = acc[3];
        __syncthreads();

        {
            int unit = u0 + gu;
            const float* xgd = g_xg[dir] + (size_t)(tidx * Bb + gb) * G4 + unit;
            float zi = zr[gu * 16 + gb]        + xgd[0];
            float zf = zr[(8 + gu) * 16 + gb]  + xgd[Hh];
            float zg = zr[(16 + gu) * 16 + gb] + xgd[2 * Hh];
            float zo = zr[(24 + gu) * 16 + gb] + xgd[3 * Hh];
            float ig = 1.f / (1.f + expf(-zi));
            float fg = 1.f / (1.f + expf(-zf));
            float gg = tanhf(zg);
            float og = 1.f / (1.f + expf(-zo));
            creg = fg * creg + ig * gg;
            float h = og * tanhf(creg);
            __half hh = __float2half_rn(h);
            g_hh[(t & 1) ^ 1][dir][gb * Hh + unit] = hh;
            if (mode == 0)
                g_x1h[(size_t)(tidx * Bb + gb) * 1024 + (dir << 9) + unit] = hh;
            else
                g_hfinh[(size_t)gb * (Ss * 1024) + tidx * 1024 + (dir << 9) + unit] = hh;
        }

        __syncthreads();
        if (tid == 0) {
            __threadfence();
            unsigned arrived = atomicAdd(&g_bar_cnt[dir], 1u);
            mygen++;
            if (arrived == 63u) {
                g_bar_cnt[dir] = 0u;
                asm volatile("red.release.gpu.global.add.u32 [%0], 1;"
                             :: "l"(&g_bar_gen[dir]) : "memory");
            } else {
                while (ld_acq(&g_bar_gen[dir]) != mygen) { }
            }
        }
        __syncthreads();
    }
}

// ---------------- launch ----------------
extern "C" void kernel_launch(void* const* d_in, const int* in_sizes, int n_in,
                              void* d_out, int out_size)
{
    const int*   tok  = (const int*)d_in[0];
    const float* ew   = (const float*)d_in[1];
    const float* Wih0f = (const float*)d_in[2],  *Whh0f = (const float*)d_in[3];
    const float* bih0f = (const float*)d_in[4],  *bhh0f = (const float*)d_in[5];
    const float* Wih0b = (const float*)d_in[6],  *Whh0b = (const float*)d_in[7];
    const float* bih0b = (const float*)d_in[8],  *bhh0b = (const float*)d_in[9];
    const float* Wih1f = (const float*)d_in[10], *Whh1f = (const float*)d_in[11];
    const float* bih1f = (const float*)d_in[12], *bhh1f = (const float*)d_in[13];
    const float* Wih1b = (const float*)d_in[14], *Whh1b = (const float*)d_in[15];
    const float* bih1b = (const float*)d_in[16], *bhh1b = (const float*)d_in[17];
    const float* linw = (const float*)d_in[18],  *linb  = (const float*)d_in[19];
    float* out = (float*)d_out;

    __half *px0, *px1, *phf;
    float *pxg, *pbias;
    cudaGetSymbolAddress((void**)&px0, g_x0h);
    cudaGetSymbolAddress((void**)&px1, g_x1h);
    cudaGetSymbolAddress((void**)&pxg, g_xg);
    cudaGetSymbolAddress((void**)&phf, g_hfinh);
    cudaGetSymbolAddress((void**)&pbias, g_bias);

    cudaFuncSetAttribute(gemm_mma, cudaFuncAttributeMaxDynamicSharedMemorySize, GEMM_DSM);
    cudaFuncSetAttribute(lstm_persist, cudaFuncAttributeMaxDynamicSharedMemorySize, LSTM_DSM);

    embed_kernel<<<MBr, 128>>>(tok, ew);

    // ---- layer 0 ----
    bias_comb<<<8, 256>>>(bih0f, bhh0f, bih0b, bhh0b);
    gemm_mma<<<dim3(16, 32), 256, GEMM_DSM>>>(px0, Wih0f, Wih0b, pbias, pxg, 512, 0);
    lstm_persist<<<dim3(64, 2), 128, LSTM_DSM>>>(Whh0f, Whh0b, 0);

    // ---- layer 1 ----
    bias_comb<<<8, 256>>>(bih1f, bhh1f, bih1b, bhh1b);
    gemm_mma<<<dim3(16, 32), 256, GEMM_DSM>>>(px1, Wih1f, Wih1b, pbias, pxg, 1024, 0);
    lstm_persist<<<dim3(64, 2), 128, LSTM_DSM>>>(Whh1f, Whh1b, 1);

    // ---- final projection (lin_w fp32 read directly) ----
    gemm_mma<<<dim3(16, 250), 256, GEMM_DSM>>>(phf, linw, linw, linb, out, 1024, 1);
}